// round 1
// baseline (speedup 1.0000x reference)
#include <cuda_runtime.h>
#include <cmath>

#define N_NODES 20000
#define N_EDGES 320000
#define CDIM    128
#define HEADS   8

// ---------------- scratch (device globals; no allocation allowed) ----------------
__device__ __align__(16) float g_sln[N_NODES * CDIM];
__device__ __align__(16) float g_q  [N_NODES * CDIM];
__device__ __align__(16) float g_k  [N_NODES * CDIM];
__device__ __align__(16) float g_h1 [N_NODES * CDIM];
__device__ __align__(16) float g_h2 [N_NODES * CDIM];
__device__ __align__(16) float g_x3 [N_NODES * 3 * CDIM];
__device__ __align__(16) float g_val[N_NODES * 3 * CDIM];
__device__ __align__(16) float g_rattn[(size_t)N_EDGES * CDIM];
__device__ __align__(16) float g_rproj[(size_t)N_EDGES * 3 * CDIM];
__device__ __align__(16) float g_alpha[N_EDGES * HEADS];
__device__ unsigned g_m[N_NODES * HEADS];
__device__ float    g_z[N_NODES * HEADS];

// order-preserving float<->uint map for atomicMax on floats of any sign
__device__ __forceinline__ unsigned enc_f(float x) {
    unsigned u = __float_as_uint(x);
    return (u & 0x80000000u) ? ~u : (u | 0x80000000u);
}
__device__ __forceinline__ float dec_f(unsigned u) {
    u = (u & 0x80000000u) ? (u & 0x7fffffffu) : ~u;
    return __uint_as_float(u);
}

// ---------------- init accumulators (must reset every replay) ----------------
__global__ void init_kernel() {
    int i = blockIdx.x * blockDim.x + threadIdx.x;
    if (i < N_NODES * HEADS) {
        g_m[i] = 0x007FFFFFu;  // enc(-inf)
        g_z[i] = 0.0f;
    }
}

// ---------------- layernorm: s -> g_sln, and seed out_s with s_ln ----------------
__global__ void ln_kernel(const float* __restrict__ s, const float* __restrict__ g,
                          const float* __restrict__ b, float* __restrict__ out_s) {
    int n = blockIdx.x;
    int c = threadIdx.x;  // 128
    float x = s[n * CDIM + c];
    __shared__ float red[4];
    int lane = c & 31, w = c >> 5;
    float sum = x;
    #pragma unroll
    for (int o = 16; o > 0; o >>= 1) sum += __shfl_xor_sync(0xffffffffu, sum, o);
    if (lane == 0) red[w] = sum;
    __syncthreads();
    float mean = (red[0] + red[1] + red[2] + red[3]) * (1.0f / 128.0f);
    float d = x - mean;
    float sq = d * d;
    #pragma unroll
    for (int o = 16; o > 0; o >>= 1) sq += __shfl_xor_sync(0xffffffffu, sq, o);
    __syncthreads();
    if (lane == 0) red[w] = sq;
    __syncthreads();
    float var = (red[0] + red[1] + red[2] + red[3]) * (1.0f / 128.0f);
    float y = d * rsqrtf(var + 1e-5f) * g[c] + b[c];
    g_sln[n * CDIM + c] = y;
    out_s[n * CDIM + c] = y;
}

// ---------------- generic K=128 GEMM: C = act(A[M,128] @ B[128,Nc] + bias) ----------------
// ACT: 0 = identity, 1 = silu
template <int ACT>
__global__ void __launch_bounds__(256)
gemm_k128(const float* __restrict__ A, const float* __restrict__ B,
          const float* __restrict__ bias, float* __restrict__ Cmat,
          int M, int Nc) {
    __shared__ float As[32][128];  // [k][m]
    __shared__ float Bs[32][128];  // [k][n]
    const int bm = blockIdx.x * 128;
    const int bn = blockIdx.y * 128;
    const int tid = threadIdx.x;
    const int tx = tid & 15, ty = tid >> 4;

    float acc[8][8];
    #pragma unroll
    for (int i = 0; i < 8; i++)
        #pragma unroll
        for (int j = 0; j < 8; j++) acc[i][j] = 0.0f;

    for (int k0 = 0; k0 < 128; k0 += 32) {
        #pragma unroll
        for (int r = 0; r < 4; r++) {
            int idx = tid + r * 256;           // 0..1023
            int row = idx >> 3;                // 0..127
            int kc = (idx & 7) << 2;           // 0..28
            float4 a4 = make_float4(0.f, 0.f, 0.f, 0.f);
            if (bm + row < M)
                a4 = *(const float4*)(A + (size_t)(bm + row) * 128 + k0 + kc);
            As[kc + 0][row] = a4.x;
            As[kc + 1][row] = a4.y;
            As[kc + 2][row] = a4.z;
            As[kc + 3][row] = a4.w;
        }
        #pragma unroll
        for (int r = 0; r < 4; r++) {
            int idx = tid + r * 256;
            int row = idx >> 5;                // 0..31
            int cc = (idx & 31) << 2;          // 0..124
            *(float4*)&Bs[row][cc] = *(const float4*)(B + (size_t)(k0 + row) * Nc + bn + cc);
        }
        __syncthreads();
        #pragma unroll
        for (int k = 0; k < 32; k++) {
            float ra[8], rb[8];
            *(float4*)&ra[0] = *(const float4*)&As[k][ty * 8];
            *(float4*)&ra[4] = *(const float4*)&As[k][ty * 8 + 4];
            *(float4*)&rb[0] = *(const float4*)&Bs[k][tx * 8];
            *(float4*)&rb[4] = *(const float4*)&Bs[k][tx * 8 + 4];
            #pragma unroll
            for (int i = 0; i < 8; i++)
                #pragma unroll
                for (int j = 0; j < 8; j++)
                    acc[i][j] = fmaf(ra[i], rb[j], acc[i][j]);
        }
        __syncthreads();
    }

    float bv[8];
    #pragma unroll
    for (int j = 0; j < 8; j++) bv[j] = bias[bn + tx * 8 + j];
    #pragma unroll
    for (int i = 0; i < 8; i++) {
        int row = bm + ty * 8 + i;
        if (row < M) {
            #pragma unroll
            for (int j = 0; j < 8; j++) {
                float v = acc[i][j] + bv[j];
                if (ACT) v = v / (1.0f + expf(-v));
                Cmat[(size_t)row * Nc + bn + tx * 8 + j] = v;
            }
        }
    }
}

// ---------------- alpha[e,h] = sum_d q[dst]*k[src]*r_attn, + segment max ----------------
__global__ void alpha_kernel(const int* __restrict__ ei) {
    int warp = (blockIdx.x * blockDim.x + threadIdx.x) >> 5;
    if (warp >= N_EDGES) return;
    int lane = threadIdx.x & 31;
    int src = ei[warp];
    int dst = ei[N_EDGES + warp];
    float4 qv = *(const float4*)&g_q[(size_t)dst * CDIM + lane * 4];
    float4 kv = *(const float4*)&g_k[(size_t)src * CDIM + lane * 4];
    float4 rv = *(const float4*)&g_rattn[(size_t)warp * CDIM + lane * 4];
    float p = qv.x * kv.x * rv.x + qv.y * kv.y * rv.y + qv.z * kv.z * rv.z + qv.w * kv.w * rv.w;
    p += __shfl_xor_sync(0xffffffffu, p, 1);
    p += __shfl_xor_sync(0xffffffffu, p, 2);
    if ((lane & 3) == 0) {
        int h = lane >> 2;
        g_alpha[(size_t)warp * HEADS + h] = p;
        atomicMax(&g_m[dst * HEADS + h], enc_f(p));
    }
}

// ---------------- e = exp(alpha - m[dst]); z[dst] += e ----------------
__global__ void exp_kernel(const int* __restrict__ ei) {
    int i = blockIdx.x * blockDim.x + threadIdx.x;
    if (i >= N_EDGES * HEADS) return;
    int e = i >> 3;
    int h = i & 7;
    int dst = ei[N_EDGES + e];
    float m = dec_f(g_m[dst * HEADS + h]);
    if (!isfinite(m)) m = 0.0f;
    float ex = expf(g_alpha[i] - m);
    g_alpha[i] = ex;
    atomicAdd(&g_z[dst * HEADS + h], ex);
}

// ---------------- per-edge message + scatter-add ----------------
__global__ void msg_kernel(const int* __restrict__ ei, const float* __restrict__ dir,
                           const float* __restrict__ dij, const float* __restrict__ v,
                           float* __restrict__ out_s, float* __restrict__ out_v) {
    int e = blockIdx.x;
    int c = threadIdx.x;  // 128
    int src = ei[e];
    int dst = ei[N_EDGES + e];
    float d = dij[e];
    float cc = (d < 5.0f) ? 0.5f * (cosf(d * 0.62831853071795865f) + 1.0f) : 0.0f;

    const float* rp  = g_rproj + (size_t)e * 384;
    const float* x3s = g_x3 + (size_t)src * 384;
    const float* vs  = g_val + (size_t)src * 384;
    const float* al  = g_alpha + (size_t)e * HEADS;

    float msg[3];
    #pragma unroll
    for (int t = 0; t < 3; t++) {
        int j = c + t * 128;
        int h = j / 48;
        float a = al[h] / (g_z[dst * HEADS + h] + 1e-16f);
        msg[t] = rp[j] * x3s[j] * cc + a * vs[j];
    }

    atomicAdd(&out_s[(size_t)dst * 128 + c], msg[0]);
    float d0 = dir[e * 3 + 0], d1 = dir[e * 3 + 1], d2 = dir[e * 3 + 2];
    const float* vsrc = v + (size_t)src * 384;
    atomicAdd(&out_v[(size_t)dst * 384 + c],        d0 * msg[1] + msg[2] * vsrc[c]);
    atomicAdd(&out_v[(size_t)dst * 384 + 128 + c],  d1 * msg[1] + msg[2] * vsrc[128 + c]);
    atomicAdd(&out_v[(size_t)dst * 384 + 256 + c],  d2 * msg[1] + msg[2] * vsrc[256 + c]);
}

// ---------------- launch ----------------
extern "C" void kernel_launch(void* const* d_in, const int* in_sizes, int n_in,
                              void* d_out, int out_size) {
    const float* s   = (const float*)d_in[0];
    const float* v   = (const float*)d_in[1];
    const float* dir = (const float*)d_in[2];
    const float* dij = (const float*)d_in[3];
    const float* rij = (const float*)d_in[4];
    const int*   ei  = (const int*)d_in[5];
    const float* lng = (const float*)d_in[6];
    const float* lnb = (const float*)d_in[7];
    const float* Wq  = (const float*)d_in[8];  const float* bq  = (const float*)d_in[9];
    const float* Wk  = (const float*)d_in[10]; const float* bk  = (const float*)d_in[11];
    const float* Wg1 = (const float*)d_in[12]; const float* bg1 = (const float*)d_in[13];
    const float* Wg2 = (const float*)d_in[14]; const float* bg2 = (const float*)d_in[15];
    const float* Wv1 = (const float*)d_in[16]; const float* bv1 = (const float*)d_in[17];
    const float* Wv2 = (const float*)d_in[18]; const float* bv2 = (const float*)d_in[19];
    const float* Wre = (const float*)d_in[20]; const float* bre = (const float*)d_in[21];
    const float* Wra = (const float*)d_in[22]; const float* bra = (const float*)d_in[23];

    float* out   = (float*)d_out;
    float* out_s = out;                                   // N*C
    float* out_v = out + (size_t)N_NODES * CDIM;          // N*3C
    float* out_r = out_v + (size_t)N_NODES * 3 * CDIM;    // E*C

    float *p_sln, *p_q, *p_k, *p_h1, *p_h2, *p_x3, *p_val, *p_rattn, *p_rproj;
    cudaGetSymbolAddress((void**)&p_sln,   g_sln);
    cudaGetSymbolAddress((void**)&p_q,     g_q);
    cudaGetSymbolAddress((void**)&p_k,     g_k);
    cudaGetSymbolAddress((void**)&p_h1,    g_h1);
    cudaGetSymbolAddress((void**)&p_h2,    g_h2);
    cudaGetSymbolAddress((void**)&p_x3,    g_x3);
    cudaGetSymbolAddress((void**)&p_val,   g_val);
    cudaGetSymbolAddress((void**)&p_rattn, g_rattn);
    cudaGetSymbolAddress((void**)&p_rproj, g_rproj);

    // seed outputs: v_out = v, r_out = r_ij (s_out seeded by ln_kernel)
    cudaMemcpyAsync(out_v, v,   sizeof(float) * (size_t)N_NODES * 3 * CDIM,
                    cudaMemcpyDeviceToDevice, 0);
    cudaMemcpyAsync(out_r, rij, sizeof(float) * (size_t)N_EDGES * CDIM,
                    cudaMemcpyDeviceToDevice, 0);

    init_kernel<<<(N_NODES * HEADS + 255) / 256, 256>>>();
    ln_kernel<<<N_NODES, 128>>>(s, lng, lnb, out_s);

    const int mb_n = (N_NODES + 127) / 128;   // 157
    const int mb_e = N_EDGES / 128;           // 2500
    gemm_k128<0><<<dim3(mb_n, 1), 256>>>(p_sln, Wq,  bq,  p_q,   N_NODES, 128);
    gemm_k128<0><<<dim3(mb_n, 1), 256>>>(p_sln, Wk,  bk,  p_k,   N_NODES, 128);
    gemm_k128<1><<<dim3(mb_n, 1), 256>>>(p_sln, Wg1, bg1, p_h1,  N_NODES, 128);
    gemm_k128<1><<<dim3(mb_n, 1), 256>>>(p_sln, Wv1, bv1, p_h2,  N_NODES, 128);
    gemm_k128<0><<<dim3(mb_n, 3), 256>>>(p_h1,  Wg2, bg2, p_x3,  N_NODES, 384);
    gemm_k128<0><<<dim3(mb_n, 3), 256>>>(p_h2,  Wv2, bv2, p_val, N_NODES, 384);
    gemm_k128<1><<<dim3(mb_e, 1), 256>>>(rij,   Wre, bre, p_rattn, N_EDGES, 128);
    gemm_k128<0><<<dim3(mb_e, 3), 256>>>(rij,   Wra, bra, p_rproj, N_EDGES, 384);

    alpha_kernel<<<N_EDGES / 8, 256>>>(ei);
    exp_kernel<<<(N_EDGES * HEADS + 255) / 256, 256>>>(ei);
    msg_kernel<<<N_EDGES, 128>>>(ei, dir, dij, v, out_s, out_v);
}

// round 2
// speedup vs baseline: 1.9881x; 1.9881x over previous
#include <cuda_runtime.h>
#include <cmath>
#include <cstdint>

#define N_NODES 20000
#define N_EDGES 320000
#define CDIM    128
#define HEADS   8

// ---------------- scratch (device globals; no allocation allowed) ----------------
__device__ __align__(16) float g_sln[N_NODES * CDIM];
__device__ __align__(16) float g_q  [N_NODES * CDIM];
__device__ __align__(16) float g_k  [N_NODES * CDIM];
__device__ __align__(16) float g_h1 [N_NODES * CDIM];
__device__ __align__(16) float g_h2 [N_NODES * CDIM];
__device__ __align__(16) float g_x3 [N_NODES * 3 * CDIM];
__device__ __align__(16) float g_val[N_NODES * 3 * CDIM];
__device__ __align__(16) float g_rattn[(size_t)N_EDGES * CDIM];
__device__ __align__(16) float g_rproj[(size_t)N_EDGES * 3 * CDIM];
__device__ __align__(16) float g_alpha[N_EDGES * HEADS];
__device__ unsigned g_m[N_NODES * HEADS];
__device__ float    g_z[N_NODES * HEADS];

// order-preserving float<->uint map for atomicMax on floats of any sign
__device__ __forceinline__ unsigned enc_f(float x) {
    unsigned u = __float_as_uint(x);
    return (u & 0x80000000u) ? ~u : (u | 0x80000000u);
}
__device__ __forceinline__ float dec_f(unsigned u) {
    u = (u & 0x80000000u) ? (u & 0x7fffffffu) : ~u;
    return __uint_as_float(u);
}

__device__ __forceinline__ float to_tf32(float x) {
    uint32_t u;
    asm("cvt.rna.tf32.f32 %0, %1;" : "=r"(u) : "f"(x));
    return __uint_as_float(u);
}

__device__ __forceinline__ void mma_tf32(float* c, const uint32_t* a, const uint32_t* b) {
    asm volatile(
        "mma.sync.aligned.m16n8k8.row.col.f32.tf32.tf32.f32 "
        "{%0,%1,%2,%3}, {%4,%5,%6,%7}, {%8,%9}, {%0,%1,%2,%3};"
        : "+f"(c[0]), "+f"(c[1]), "+f"(c[2]), "+f"(c[3])
        : "r"(a[0]), "r"(a[1]), "r"(a[2]), "r"(a[3]), "r"(b[0]), "r"(b[1]));
}

// ---------------- init accumulators (must reset every replay) ----------------
__global__ void init_kernel() {
    int i = blockIdx.x * blockDim.x + threadIdx.x;
    if (i < N_NODES * HEADS) {
        g_m[i] = 0x007FFFFFu;  // enc(-inf)
        g_z[i] = 0.0f;
    }
}

// ---------------- layernorm: s -> g_sln, and seed out_s with s_ln ----------------
__global__ void ln_kernel(const float* __restrict__ s, const float* __restrict__ g,
                          const float* __restrict__ b, float* __restrict__ out_s) {
    int n = blockIdx.x;
    int c = threadIdx.x;  // 128
    float x = s[n * CDIM + c];
    __shared__ float red[4];
    int lane = c & 31, w = c >> 5;
    float sum = x;
    #pragma unroll
    for (int o = 16; o > 0; o >>= 1) sum += __shfl_xor_sync(0xffffffffu, sum, o);
    if (lane == 0) red[w] = sum;
    __syncthreads();
    float mean = (red[0] + red[1] + red[2] + red[3]) * (1.0f / 128.0f);
    float d = x - mean;
    float sq = d * d;
    #pragma unroll
    for (int o = 16; o > 0; o >>= 1) sq += __shfl_xor_sync(0xffffffffu, sq, o);
    __syncthreads();
    if (lane == 0) red[w] = sq;
    __syncthreads();
    float var = (red[0] + red[1] + red[2] + red[3]) * (1.0f / 128.0f);
    float y = d * rsqrtf(var + 1e-5f) * g[c] + b[c];
    g_sln[n * CDIM + c] = y;
    out_s[n * CDIM + c] = y;
}

// ---------------- tf32 tensor-core GEMM: C = act(A[M,128] @ B[128,Nc] + bias) ----
// Block tile 128x128, K=128 in chunks of 32. 8 warps, warp tile 32x64.
// ACT: 0 = identity, 1 = silu
template <int ACT>
__global__ void __launch_bounds__(256)
gemm_tf32(const float* __restrict__ A, const float* __restrict__ B,
          const float* __restrict__ bias, float* __restrict__ Cmat,
          int M, int Nc) {
    __shared__ float As[128][36];   // [row][k], pad 36 -> frag banks 4*gid+tig (bijective)
    __shared__ float Bs[32][136];   // [k][n],  pad 136 -> frag banks 8*tig+gid (bijective)

    const int bm = blockIdx.x * 128;
    const int bn = blockIdx.y * 128;
    const int tid  = threadIdx.x;
    const int warp = tid >> 5, lane = tid & 31;
    const int gid  = lane >> 2, tig = lane & 3;
    const int wm = (warp & 3) * 32;     // warp row offset
    const int wn = (warp >> 2) * 64;    // warp col offset

    float acc[2][8][4];
    #pragma unroll
    for (int mi = 0; mi < 2; mi++)
        #pragma unroll
        for (int ni = 0; ni < 8; ni++)
            #pragma unroll
            for (int t = 0; t < 4; t++) acc[mi][ni][t] = 0.0f;

    for (int k0 = 0; k0 < 128; k0 += 32) {
        // fill As: 128 rows x 32 k
        #pragma unroll
        for (int r = 0; r < 4; r++) {
            int idx = tid + r * 256;        // 0..1023
            int row = idx >> 3;             // 0..127
            int kq  = (idx & 7) << 2;       // 0..28
            float4 a4 = make_float4(0.f, 0.f, 0.f, 0.f);
            if (bm + row < M)
                a4 = *(const float4*)(A + (size_t)(bm + row) * 128 + k0 + kq);
            As[row][kq + 0] = to_tf32(a4.x);
            As[row][kq + 1] = to_tf32(a4.y);
            As[row][kq + 2] = to_tf32(a4.z);
            As[row][kq + 3] = to_tf32(a4.w);
        }
        // fill Bs: 32 k x 128 n
        #pragma unroll
        for (int r = 0; r < 4; r++) {
            int idx = tid + r * 256;
            int krow = idx >> 5;            // 0..31
            int nq   = (idx & 31) << 2;     // 0..124
            float4 b4 = *(const float4*)(B + (size_t)(k0 + krow) * Nc + bn + nq);
            Bs[krow][nq + 0] = to_tf32(b4.x);
            Bs[krow][nq + 1] = to_tf32(b4.y);
            Bs[krow][nq + 2] = to_tf32(b4.z);
            Bs[krow][nq + 3] = to_tf32(b4.w);
        }
        __syncthreads();

        #pragma unroll
        for (int kk = 0; kk < 32; kk += 8) {
            uint32_t bf[8][2];
            #pragma unroll
            for (int ni = 0; ni < 8; ni++) {
                bf[ni][0] = __float_as_uint(Bs[kk + tig    ][wn + ni * 8 + gid]);
                bf[ni][1] = __float_as_uint(Bs[kk + tig + 4][wn + ni * 8 + gid]);
            }
            #pragma unroll
            for (int mi = 0; mi < 2; mi++) {
                uint32_t af[4];
                af[0] = __float_as_uint(As[wm + mi * 16 + gid    ][kk + tig    ]);
                af[1] = __float_as_uint(As[wm + mi * 16 + gid + 8][kk + tig    ]);
                af[2] = __float_as_uint(As[wm + mi * 16 + gid    ][kk + tig + 4]);
                af[3] = __float_as_uint(As[wm + mi * 16 + gid + 8][kk + tig + 4]);
                #pragma unroll
                for (int ni = 0; ni < 8; ni++)
                    mma_tf32(acc[mi][ni], af, bf[ni]);
            }
        }
        __syncthreads();
    }

    // epilogue: each (mi,ni) tile -> rows gid,gid+8; cols 2*tig,2*tig+1
    #pragma unroll
    for (int mi = 0; mi < 2; mi++) {
        int r0 = bm + wm + mi * 16 + gid;
        int r1 = r0 + 8;
        #pragma unroll
        for (int ni = 0; ni < 8; ni++) {
            int col = bn + wn + ni * 8 + tig * 2;
            float bb0 = bias[col], bb1 = bias[col + 1];
            float v0 = acc[mi][ni][0] + bb0;
            float v1 = acc[mi][ni][1] + bb1;
            float v2 = acc[mi][ni][2] + bb0;
            float v3 = acc[mi][ni][3] + bb1;
            if (ACT) {
                v0 = v0 / (1.0f + expf(-v0));
                v1 = v1 / (1.0f + expf(-v1));
                v2 = v2 / (1.0f + expf(-v2));
                v3 = v3 / (1.0f + expf(-v3));
            }
            if (r0 < M) { float2 o = make_float2(v0, v1); *(float2*)(Cmat + (size_t)r0 * Nc + col) = o; }
            if (r1 < M) { float2 o = make_float2(v2, v3); *(float2*)(Cmat + (size_t)r1 * Nc + col) = o; }
        }
    }
}

// ---------------- alpha[e,h] = sum_d q[dst]*k[src]*r_attn, + segment max ----------------
__global__ void alpha_kernel(const int* __restrict__ ei) {
    int warp = (blockIdx.x * blockDim.x + threadIdx.x) >> 5;
    if (warp >= N_EDGES) return;
    int lane = threadIdx.x & 31;
    int src = ei[warp];
    int dst = ei[N_EDGES + warp];
    float4 qv = *(const float4*)&g_q[(size_t)dst * CDIM + lane * 4];
    float4 kv = *(const float4*)&g_k[(size_t)src * CDIM + lane * 4];
    float4 rv = *(const float4*)&g_rattn[(size_t)warp * CDIM + lane * 4];
    float p = qv.x * kv.x * rv.x + qv.y * kv.y * rv.y + qv.z * kv.z * rv.z + qv.w * kv.w * rv.w;
    p += __shfl_xor_sync(0xffffffffu, p, 1);
    p += __shfl_xor_sync(0xffffffffu, p, 2);
    if ((lane & 3) == 0) {
        int h = lane >> 2;
        g_alpha[(size_t)warp * HEADS + h] = p;
        atomicMax(&g_m[dst * HEADS + h], enc_f(p));
    }
}

// ---------------- e = exp(alpha - m[dst]); z[dst] += e ----------------
__global__ void exp_kernel(const int* __restrict__ ei) {
    int i = blockIdx.x * blockDim.x + threadIdx.x;
    if (i >= N_EDGES * HEADS) return;
    int e = i >> 3;
    int h = i & 7;
    int dst = ei[N_EDGES + e];
    float m = dec_f(g_m[dst * HEADS + h]);
    if (!isfinite(m)) m = 0.0f;
    float ex = expf(g_alpha[i] - m);
    g_alpha[i] = ex;
    atomicAdd(&g_z[dst * HEADS + h], ex);
}

// ---------------- per-edge message + scatter-add ----------------
__global__ void msg_kernel(const int* __restrict__ ei, const float* __restrict__ dir,
                           const float* __restrict__ dij, const float* __restrict__ v,
                           float* __restrict__ out_s, float* __restrict__ out_v) {
    int e = blockIdx.x;
    int c = threadIdx.x;  // 128
    int src = ei[e];
    int dst = ei[N_EDGES + e];
    float d = dij[e];
    float cc = (d < 5.0f) ? 0.5f * (cosf(d * 0.62831853071795865f) + 1.0f) : 0.0f;

    const float* rp  = g_rproj + (size_t)e * 384;
    const float* x3s = g_x3 + (size_t)src * 384;
    const float* vs  = g_val + (size_t)src * 384;
    const float* al  = g_alpha + (size_t)e * HEADS;

    float msg[3];
    #pragma unroll
    for (int t = 0; t < 3; t++) {
        int j = c + t * 128;
        int h = j / 48;
        float a = al[h] / (g_z[dst * HEADS + h] + 1e-16f);
        msg[t] = rp[j] * x3s[j] * cc + a * vs[j];
    }

    atomicAdd(&out_s[(size_t)dst * 128 + c], msg[0]);
    float d0 = dir[e * 3 + 0], d1 = dir[e * 3 + 1], d2 = dir[e * 3 + 2];
    const float* vsrc = v + (size_t)src * 384;
    atomicAdd(&out_v[(size_t)dst * 384 + c],        d0 * msg[1] + msg[2] * vsrc[c]);
    atomicAdd(&out_v[(size_t)dst * 384 + 128 + c],  d1 * msg[1] + msg[2] * vsrc[128 + c]);
    atomicAdd(&out_v[(size_t)dst * 384 + 256 + c],  d2 * msg[1] + msg[2] * vsrc[256 + c]);
}

// ---------------- launch ----------------
extern "C" void kernel_launch(void* const* d_in, const int* in_sizes, int n_in,
                              void* d_out, int out_size) {
    const float* s   = (const float*)d_in[0];
    const float* v   = (const float*)d_in[1];
    const float* dir = (const float*)d_in[2];
    const float* dij = (const float*)d_in[3];
    const float* rij = (const float*)d_in[4];
    const int*   ei  = (const int*)d_in[5];
    const float* lng = (const float*)d_in[6];
    const float* lnb = (const float*)d_in[7];
    const float* Wq  = (const float*)d_in[8];  const float* bq  = (const float*)d_in[9];
    const float* Wk  = (const float*)d_in[10]; const float* bk  = (const float*)d_in[11];
    const float* Wg1 = (const float*)d_in[12]; const float* bg1 = (const float*)d_in[13];
    const float* Wg2 = (const float*)d_in[14]; const float* bg2 = (const float*)d_in[15];
    const float* Wv1 = (const float*)d_in[16]; const float* bv1 = (const float*)d_in[17];
    const float* Wv2 = (const float*)d_in[18]; const float* bv2 = (const float*)d_in[19];
    const float* Wre = (const float*)d_in[20]; const float* bre = (const float*)d_in[21];
    const float* Wra = (const float*)d_in[22]; const float* bra = (const float*)d_in[23];

    float* out   = (float*)d_out;
    float* out_s = out;                                   // N*C
    float* out_v = out + (size_t)N_NODES * CDIM;          // N*3C
    float* out_r = out_v + (size_t)N_NODES * 3 * CDIM;    // E*C

    float *p_sln, *p_q, *p_k, *p_h1, *p_h2, *p_x3, *p_val, *p_rattn, *p_rproj;
    cudaGetSymbolAddress((void**)&p_sln,   g_sln);
    cudaGetSymbolAddress((void**)&p_q,     g_q);
    cudaGetSymbolAddress((void**)&p_k,     g_k);
    cudaGetSymbolAddress((void**)&p_h1,    g_h1);
    cudaGetSymbolAddress((void**)&p_h2,    g_h2);
    cudaGetSymbolAddress((void**)&p_x3,    g_x3);
    cudaGetSymbolAddress((void**)&p_val,   g_val);
    cudaGetSymbolAddress((void**)&p_rattn, g_rattn);
    cudaGetSymbolAddress((void**)&p_rproj, g_rproj);

    // seed outputs: v_out = v, r_out = r_ij (s_out seeded by ln_kernel)
    cudaMemcpyAsync(out_v, v,   sizeof(float) * (size_t)N_NODES * 3 * CDIM,
                    cudaMemcpyDeviceToDevice, 0);
    cudaMemcpyAsync(out_r, rij, sizeof(float) * (size_t)N_EDGES * CDIM,
                    cudaMemcpyDeviceToDevice, 0);

    init_kernel<<<(N_NODES * HEADS + 255) / 256, 256>>>();
    ln_kernel<<<N_NODES, 128>>>(s, lng, lnb, out_s);

    const int mb_n = (N_NODES + 127) / 128;   // 157
    const int mb_e = N_EDGES / 128;           // 2500
    gemm_tf32<0><<<dim3(mb_n, 1), 256>>>(p_sln, Wq,  bq,  p_q,   N_NODES, 128);
    gemm_tf32<0><<<dim3(mb_n, 1), 256>>>(p_sln, Wk,  bk,  p_k,   N_NODES, 128);
    gemm_tf32<1><<<dim3(mb_n, 1), 256>>>(p_sln, Wg1, bg1, p_h1,  N_NODES, 128);
    gemm_tf32<1><<<dim3(mb_n, 1), 256>>>(p_sln, Wv1, bv1, p_h2,  N_NODES, 128);
    gemm_tf32<0><<<dim3(mb_n, 3), 256>>>(p_h1,  Wg2, bg2, p_x3,  N_NODES, 384);
    gemm_tf32<0><<<dim3(mb_n, 3), 256>>>(p_h2,  Wv2, bv2, p_val, N_NODES, 384);
    gemm_tf32<1><<<dim3(mb_e, 1), 256>>>(rij,   Wre, bre, p_rattn, N_EDGES, 128);
    gemm_tf32<0><<<dim3(mb_e, 3), 256>>>(rij,   Wra, bra, p_rproj, N_EDGES, 384);

    alpha_kernel<<<N_EDGES / 8, 256>>>(ei);
    exp_kernel<<<(N_EDGES * HEADS + 255) / 256, 256>>>(ei);
    msg_kernel<<<N_EDGES, 128>>>(ei, dir, dij, v, out_s, out_v);
}